// round 14
// baseline (speedup 1.0000x reference)
#include <cuda_runtime.h>

#define N_NODES 100000
#define D       64
#define N_EDGES 1250000
#define NBLK    98            // ceil(N_NODES / 1024) scan blocks per array

// ---- scratch (allocation-free rule: __device__ globals) ----
__device__ __align__(16) float g_agg[N_NODES * D];   // mean of X[src] at dst
__device__ __align__(16) float g_h[N_NODES * D];     // relu(agg@Wl + b + X@Wr)
__device__ int g_incnt[N_NODES];
__device__ int g_outcnt[N_NODES];
__device__ int g_inptr[N_NODES + 1];
__device__ int g_outptr[N_NODES + 1];
__device__ int g_incur[N_NODES];
__device__ int g_outcur[N_NODES];
__device__ int g_adj_in[N_EDGES];     // src per dst-sorted edge
__device__ int g_adj_out[N_EDGES];    // dst per src-sorted edge
__device__ int g_bsum[2 * NBLK];
__device__ int g_idx64;

// Edge accessor robust to int32-vs-int64 edge_index.
__device__ __forceinline__ void load_edge(const void* __restrict__ ei,
                                          int e, int is64, int& r, int& c) {
    if (is64) {
        const long long* p = (const long long*)ei;
        r = (int)p[e];
        c = (int)p[N_EDGES + e];
    } else {
        const int* p = (const int*)ei;
        r = p[e];
        c = p[N_EDGES + e];
    }
}

// ---------------------------------------------------------------------------
// K1: zero histograms + dtype detect. Runs every replay.
// ---------------------------------------------------------------------------
__global__ void k_init(const long long* __restrict__ ei64) {
    int i = blockIdx.x * blockDim.x + threadIdx.x;
    if (i == 0) {
        int ok = 1;
        for (int k = 0; k < 32; k++) {
            long long v = ei64[k];
            if (v < 0 || v >= N_NODES) { ok = 0; break; }
        }
        g_idx64 = ok;
    }
    if (i < N_NODES) { g_incnt[i] = 0; g_outcnt[i] = 0; }
}

// ---------------------------------------------------------------------------
// K2: degree histograms.
// ---------------------------------------------------------------------------
__global__ void k_hist(const void* __restrict__ ei) {
    int e = blockIdx.x * blockDim.x + threadIdx.x;
    if (e >= N_EDGES) return;
    int is64 = g_idx64;
    int r, c;
    load_edge(ei, e, is64, r, c);
    atomicAdd(&g_outcnt[r], 1);
    atomicAdd(&g_incnt[c], 1);
}

// ---------------------------------------------------------------------------
// K3a: per-block exclusive scan (1024 elems/block). blocks [0,98): incnt,
//      blocks [98,196): outcnt.
// ---------------------------------------------------------------------------
__global__ __launch_bounds__(1024) void k_scan1() {
    __shared__ int ss[1024];
    int arr = blockIdx.x < NBLK ? 0 : 1;
    int blk = arr == 0 ? blockIdx.x : blockIdx.x - NBLK;
    int idx = blk * 1024 + threadIdx.x;
    const int* cnt = arr == 0 ? g_incnt : g_outcnt;
    int* ptr = arr == 0 ? g_inptr : g_outptr;
    int val = (idx < N_NODES) ? cnt[idx] : 0;
    ss[threadIdx.x] = val;
    __syncthreads();
#pragma unroll
    for (int off = 1; off < 1024; off <<= 1) {
        int t = (threadIdx.x >= off) ? ss[threadIdx.x - off] : 0;
        __syncthreads();
        ss[threadIdx.x] += t;
        __syncthreads();
    }
    if (idx < N_NODES) ptr[idx] = ss[threadIdx.x] - val;   // exclusive
    if (threadIdx.x == 1023) g_bsum[blockIdx.x] = ss[1023];
}

// K3b: scan the 2x98 block sums (parallel Hillis-Steele, both arrays at once).
__global__ __launch_bounds__(256) void k_scan2() {
    __shared__ int ss[256];
    int t = threadIdx.x;
    int half = t >> 7;          // 0: in-array, 1: out-array
    int i = t & 127;
    int val = (i < NBLK) ? g_bsum[half * NBLK + i] : 0;
    ss[t] = val;
    __syncthreads();
#pragma unroll
    for (int off = 1; off < 128; off <<= 1) {
        int v = (i >= off) ? ss[t - off] : 0;
        __syncthreads();
        ss[t] += v;
        __syncthreads();
    }
    if (i < NBLK) g_bsum[half * NBLK + i] = ss[t] - val;   // exclusive
}

// K3c: add block offsets; init cursors; set sentinels.
__global__ __launch_bounds__(1024) void k_scan3() {
    int arr = blockIdx.x < NBLK ? 0 : 1;
    int blk = arr == 0 ? blockIdx.x : blockIdx.x - NBLK;
    int idx = blk * 1024 + threadIdx.x;
    int off = g_bsum[blockIdx.x];
    if (idx < N_NODES) {
        if (arr == 0) { int v = g_inptr[idx] + off;  g_inptr[idx] = v;  g_incur[idx] = v; }
        else          { int v = g_outptr[idx] + off; g_outptr[idx] = v; g_outcur[idx] = v; }
    }
    if (blockIdx.x == 0 && threadIdx.x == 0) {
        g_inptr[N_NODES] = N_EDGES;
        g_outptr[N_NODES] = N_EDGES;
    }
}

// ---------------------------------------------------------------------------
// K4: permute edges into both adjacency arrays.
// ---------------------------------------------------------------------------
__global__ void k_permute(const void* __restrict__ ei) {
    int e = blockIdx.x * blockDim.x + threadIdx.x;
    if (e >= N_EDGES) return;
    int is64 = g_idx64;
    int r, c;
    load_edge(ei, e, is64, r, c);
    int p0 = atomicAdd(&g_incur[c], 1);
    g_adj_in[p0] = r;
    int p1 = atomicAdd(&g_outcur[r], 1);
    g_adj_out[p1] = c;
}

// ---------------------------------------------------------------------------
// K5: agg[v] = mean over in-neighbors of X[src]. Warp per node, lane = float2.
// ---------------------------------------------------------------------------
__global__ __launch_bounds__(256) void k_agg(const float2* __restrict__ X2) {
    int warp = (blockIdx.x * blockDim.x + threadIdx.x) >> 5;
    int lane = threadIdx.x & 31;
    if (warp >= N_NODES) return;
    int s = g_inptr[warp];
    int e = g_inptr[warp + 1];
    float2 acc = make_float2(0.f, 0.f);
    int j = s;
    for (; j + 1 < e; j += 2) {
        int c0 = g_adj_in[j];
        int c1 = g_adj_in[j + 1];
        float2 v0 = __ldg(&X2[(long long)c0 * 32 + lane]);
        float2 v1 = __ldg(&X2[(long long)c1 * 32 + lane]);
        acc.x += v0.x + v1.x;
        acc.y += v0.y + v1.y;
    }
    if (j < e) {
        int c0 = g_adj_in[j];
        float2 v0 = __ldg(&X2[(long long)c0 * 32 + lane]);
        acc.x += v0.x; acc.y += v0.y;
    }
    float inv = 1.f / (float)max(e - s, 1);
    float2 o = make_float2(acc.x * inv, acc.y * inv);
    reinterpret_cast<float2*>(g_agg)[(long long)warp * 32 + lane] = o;
}

// ---------------------------------------------------------------------------
// K6: h = relu( agg @ Wl + b + X @ Wr ).
// 64-node tile, 256 threads. Warp = 32 nodes x 16 outputs; thread = 1 node
// x 16 outputs. Weight LDS are warp-uniform (broadcast, ~free crossbar);
// a/x LDS are conflict-free LDS.32. Per k: 10 LDS (384 crossbar bytes/warp)
// -> 32 FFMA, vs old 4 LDS.128 (2KB/warp) -> 32 FFMA.
// Dynamic smem 64 KB: sWl[4096] sWr[4096] saT[4096] sxT[4096], k-major tiles.
// ---------------------------------------------------------------------------
__global__ __launch_bounds__(256) void k_h(const float* __restrict__ X,
                                           const float* __restrict__ Wl,
                                           const float* __restrict__ Wr,
                                           const float* __restrict__ b) {
    extern __shared__ float s[];
    float* sWl = s;
    float* sWr = s + 4096;
    float* saT = s + 8192;
    float* sxT = s + 12288;

    const int t = threadIdx.x;
    for (int i = t; i < 4096; i += 256) { sWl[i] = Wl[i]; sWr[i] = Wr[i]; }

    const int w    = t >> 5;            // warp 0..7
    const int lane = t & 31;
    const int nloc = (w & 1) * 32 + lane;   // node within 64-node tile
    const int jb   = (w >> 1) * 16;         // output base: 0,16,32,48

    float4 bias[4];
#pragma unroll
    for (int q = 0; q < 4; q++)
        bias[q] = reinterpret_cast<const float4*>(b)[(jb >> 2) + q];
    __syncthreads();

    const float4* A4 = reinterpret_cast<const float4*>(g_agg);
    const float4* X4 = reinterpret_cast<const float4*>(X);

    for (int base = blockIdx.x * 64; base < N_NODES; base += gridDim.x * 64) {
        // ---- load 64-node tile, transposed (k-major) ----
#pragma unroll
        for (int p = 0; p < 4; p++) {
            int fi = t + p * 256;          // 0..1023
            int node = fi & 63;
            int kq = fi >> 6;              // 0..15 (float4 index along k)
            int gnode = base + node;
            float4 va, vx;
            if (gnode < N_NODES) {
                va = A4[(long long)gnode * 16 + kq];
                vx = X4[(long long)gnode * 16 + kq];
            } else {
                va = make_float4(0.f, 0.f, 0.f, 0.f);
                vx = va;
            }
            int kb = kq * 4;
            saT[(kb + 0) * 64 + node] = va.x;
            saT[(kb + 1) * 64 + node] = va.y;
            saT[(kb + 2) * 64 + node] = va.z;
            saT[(kb + 3) * 64 + node] = va.w;
            sxT[(kb + 0) * 64 + node] = vx.x;
            sxT[(kb + 1) * 64 + node] = vx.y;
            sxT[(kb + 2) * 64 + node] = vx.z;
            sxT[(kb + 3) * 64 + node] = vx.w;
        }
        __syncthreads();

        // ---- compute 1 node x 16 outputs ----
        float acc[16];
#pragma unroll
        for (int q = 0; q < 4; q++) {
            acc[q * 4 + 0] = bias[q].x; acc[q * 4 + 1] = bias[q].y;
            acc[q * 4 + 2] = bias[q].z; acc[q * 4 + 3] = bias[q].w;
        }
#pragma unroll 4
        for (int k = 0; k < 64; k++) {
            float a = saT[k * 64 + nloc];
            float x = sxT[k * 64 + nloc];
            const float4* wl4 = reinterpret_cast<const float4*>(&sWl[k * 64 + jb]);
            const float4* wr4 = reinterpret_cast<const float4*>(&sWr[k * 64 + jb]);
#pragma unroll
            for (int q = 0; q < 4; q++) {
                float4 wl = wl4[q];
                float4 wr = wr4[q];
                acc[q * 4 + 0] += a * wl.x + x * wr.x;
                acc[q * 4 + 1] += a * wl.y + x * wr.y;
                acc[q * 4 + 2] += a * wl.z + x * wr.z;
                acc[q * 4 + 3] += a * wl.w + x * wr.w;
            }
        }

        // ---- store with ReLU ----
        int gnode = base + nloc;
        if (gnode < N_NODES) {
            float4* dst = reinterpret_cast<float4*>(&g_h[(long long)gnode * 64 + jb]);
#pragma unroll
            for (int q = 0; q < 4; q++) {
                float4 o;
                o.x = fmaxf(acc[q * 4 + 0], 0.f);
                o.y = fmaxf(acc[q * 4 + 1], 0.f);
                o.z = fmaxf(acc[q * 4 + 2], 0.f);
                o.w = fmaxf(acc[q * 4 + 3], 0.f);
                dst[q] = o;
            }
        }
        __syncthreads();
    }
}

// ---------------------------------------------------------------------------
// K7: out[r] = tanh( mean over out-neighbors of (h[r]-h[c])^2 ).
//     Warp per node; h[r] held in registers; writes final output directly.
// ---------------------------------------------------------------------------
__global__ __launch_bounds__(256) void k_edge_csr(float2* __restrict__ out) {
    int warp = (blockIdx.x * blockDim.x + threadIdx.x) >> 5;
    int lane = threadIdx.x & 31;
    if (warp >= N_NODES) return;
    const float2* h2 = reinterpret_cast<const float2*>(g_h);
    float2 hr = h2[(long long)warp * 32 + lane];
    int s = g_outptr[warp];
    int e = g_outptr[warp + 1];
    float2 acc = make_float2(0.f, 0.f);
    int j = s;
    for (; j + 1 < e; j += 2) {
        int c0 = g_adj_out[j];
        int c1 = g_adj_out[j + 1];
        float2 v0 = __ldg(&h2[(long long)c0 * 32 + lane]);
        float2 v1 = __ldg(&h2[(long long)c1 * 32 + lane]);
        float d0x = hr.x - v0.x, d0y = hr.y - v0.y;
        float d1x = hr.x - v1.x, d1y = hr.y - v1.y;
        acc.x += d0x * d0x + d1x * d1x;
        acc.y += d0y * d0y + d1y * d1y;
    }
    if (j < e) {
        int c0 = g_adj_out[j];
        float2 v0 = __ldg(&h2[(long long)c0 * 32 + lane]);
        float dx = hr.x - v0.x, dy = hr.y - v0.y;
        acc.x += dx * dx;
        acc.y += dy * dy;
    }
    float inv = 1.f / (float)max(e - s, 1);
    float2 o = make_float2(tanhf(acc.x * inv), tanhf(acc.y * inv));
    out[(long long)warp * 32 + lane] = o;
}

// ---------------------------------------------------------------------------
extern "C" void kernel_launch(void* const* d_in, const int* in_sizes, int n_in,
                              void* d_out, int out_size) {
    const float* X  = (const float*)d_in[0];
    const void*  ei = d_in[1];
    const float* Wl = (const float*)d_in[2];
    const float* Wr = (const float*)d_in[3];
    const float* b  = (const float*)d_in[4];
    float* out = (float*)d_out;

    const int KH_SMEM = 16384 * sizeof(float);   // 64 KB
    static int attr_done = 0;
    if (!attr_done) {
        cudaFuncSetAttribute(k_h, cudaFuncAttributeMaxDynamicSharedMemorySize,
                             KH_SMEM);
        attr_done = 1;
    }

    k_init<<<(N_NODES + 1023) / 1024, 1024>>>((const long long*)ei);
    k_hist<<<(N_EDGES + 511) / 512, 512>>>(ei);
    k_scan1<<<2 * NBLK, 1024>>>();
    k_scan2<<<1, 256>>>();
    k_scan3<<<2 * NBLK, 1024>>>();
    k_permute<<<(N_EDGES + 511) / 512, 512>>>(ei);
    k_agg<<<(N_NODES * 32 + 255) / 256, 256>>>((const float2*)X);
    k_h<<<444, 256, KH_SMEM>>>(X, Wl, Wr, b);
    k_edge_csr<<<(N_NODES * 32 + 255) / 256, 256>>>((float2*)out);
}

// round 15
// speedup vs baseline: 1.0079x; 1.0079x over previous
#include <cuda_runtime.h>

#define N_NODES 100000
#define D       64
#define N_EDGES 1250000
#define NBLK    98            // ceil(N_NODES / 1024) scan blocks per array

// ---- scratch (allocation-free rule: __device__ globals) ----
__device__ __align__(16) float g_agg[N_NODES * D];   // mean of X[src] at dst
__device__ __align__(16) float g_h[N_NODES * D];     // relu(agg@Wl + b + X@Wr)
__device__ int g_incnt[N_NODES];
__device__ int g_outcnt[N_NODES];
__device__ int g_inptr[N_NODES + 1];
__device__ int g_outptr[N_NODES + 1];
__device__ int g_incur[N_NODES];
__device__ int g_outcur[N_NODES];
__device__ int g_adj_in[N_EDGES];     // src per dst-sorted edge
__device__ int g_adj_out[N_EDGES];    // dst per src-sorted edge
__device__ int g_bsum[2 * NBLK];
__device__ int g_idx64;

// Edge accessor robust to int32-vs-int64 edge_index.
__device__ __forceinline__ void load_edge(const void* __restrict__ ei,
                                          int e, int is64, int& r, int& c) {
    if (is64) {
        const long long* p = (const long long*)ei;
        r = (int)p[e];
        c = (int)p[N_EDGES + e];
    } else {
        const int* p = (const int*)ei;
        r = p[e];
        c = p[N_EDGES + e];
    }
}

// ---------------------------------------------------------------------------
// K1: zero histograms + dtype detect. Runs every replay.
// ---------------------------------------------------------------------------
__global__ void k_init(const long long* __restrict__ ei64) {
    int i = blockIdx.x * blockDim.x + threadIdx.x;
    if (i == 0) {
        int ok = 1;
        for (int k = 0; k < 32; k++) {
            long long v = ei64[k];
            if (v < 0 || v >= N_NODES) { ok = 0; break; }
        }
        g_idx64 = ok;
    }
    if (i < N_NODES) { g_incnt[i] = 0; g_outcnt[i] = 0; }
}

// ---------------------------------------------------------------------------
// K2: degree histograms.
// ---------------------------------------------------------------------------
__global__ void k_hist(const void* __restrict__ ei) {
    int e = blockIdx.x * blockDim.x + threadIdx.x;
    if (e >= N_EDGES) return;
    int is64 = g_idx64;
    int r, c;
    load_edge(ei, e, is64, r, c);
    atomicAdd(&g_outcnt[r], 1);
    atomicAdd(&g_incnt[c], 1);
}

// ---------------------------------------------------------------------------
// K3a: per-block exclusive scan (1024 elems/block). blocks [0,98): incnt,
//      blocks [98,196): outcnt.
// ---------------------------------------------------------------------------
__global__ __launch_bounds__(1024) void k_scan1() {
    __shared__ int ss[1024];
    int arr = blockIdx.x < NBLK ? 0 : 1;
    int blk = arr == 0 ? blockIdx.x : blockIdx.x - NBLK;
    int idx = blk * 1024 + threadIdx.x;
    const int* cnt = arr == 0 ? g_incnt : g_outcnt;
    int* ptr = arr == 0 ? g_inptr : g_outptr;
    int val = (idx < N_NODES) ? cnt[idx] : 0;
    ss[threadIdx.x] = val;
    __syncthreads();
#pragma unroll
    for (int off = 1; off < 1024; off <<= 1) {
        int t = (threadIdx.x >= off) ? ss[threadIdx.x - off] : 0;
        __syncthreads();
        ss[threadIdx.x] += t;
        __syncthreads();
    }
    if (idx < N_NODES) ptr[idx] = ss[threadIdx.x] - val;   // exclusive
    if (threadIdx.x == 1023) g_bsum[blockIdx.x] = ss[1023];
}

// K3b: scan the 2x98 block sums (parallel Hillis-Steele, both arrays at once).
__global__ __launch_bounds__(256) void k_scan2() {
    __shared__ int ss[256];
    int t = threadIdx.x;
    int half = t >> 7;          // 0: in-array, 1: out-array
    int i = t & 127;
    int val = (i < NBLK) ? g_bsum[half * NBLK + i] : 0;
    ss[t] = val;
    __syncthreads();
#pragma unroll
    for (int off = 1; off < 128; off <<= 1) {
        int v = (i >= off) ? ss[t - off] : 0;
        __syncthreads();
        ss[t] += v;
        __syncthreads();
    }
    if (i < NBLK) g_bsum[half * NBLK + i] = ss[t] - val;   // exclusive
}

// K3c: add block offsets; init cursors; set sentinels.
__global__ __launch_bounds__(1024) void k_scan3() {
    int arr = blockIdx.x < NBLK ? 0 : 1;
    int blk = arr == 0 ? blockIdx.x : blockIdx.x - NBLK;
    int idx = blk * 1024 + threadIdx.x;
    int off = g_bsum[blockIdx.x];
    if (idx < N_NODES) {
        if (arr == 0) { int v = g_inptr[idx] + off;  g_inptr[idx] = v;  g_incur[idx] = v; }
        else          { int v = g_outptr[idx] + off; g_outptr[idx] = v; g_outcur[idx] = v; }
    }
    if (blockIdx.x == 0 && threadIdx.x == 0) {
        g_inptr[N_NODES] = N_EDGES;
        g_outptr[N_NODES] = N_EDGES;
    }
}

// ---------------------------------------------------------------------------
// K4: permute edges into both adjacency arrays.
// ---------------------------------------------------------------------------
__global__ void k_permute(const void* __restrict__ ei) {
    int e = blockIdx.x * blockDim.x + threadIdx.x;
    if (e >= N_EDGES) return;
    int is64 = g_idx64;
    int r, c;
    load_edge(ei, e, is64, r, c);
    int p0 = atomicAdd(&g_incur[c], 1);
    g_adj_in[p0] = r;
    int p1 = atomicAdd(&g_outcur[r], 1);
    g_adj_out[p1] = c;
}

// ---------------------------------------------------------------------------
// K5: agg[v] = mean over in-neighbors of X[src]. Warp per node, lane = float2.
// ---------------------------------------------------------------------------
__global__ __launch_bounds__(256) void k_agg(const float2* __restrict__ X2) {
    int warp = (blockIdx.x * blockDim.x + threadIdx.x) >> 5;
    int lane = threadIdx.x & 31;
    if (warp >= N_NODES) return;
    int s = g_inptr[warp];
    int e = g_inptr[warp + 1];
    float2 acc = make_float2(0.f, 0.f);
    int j = s;
    for (; j + 1 < e; j += 2) {
        int c0 = g_adj_in[j];
        int c1 = g_adj_in[j + 1];
        float2 v0 = __ldg(&X2[(long long)c0 * 32 + lane]);
        float2 v1 = __ldg(&X2[(long long)c1 * 32 + lane]);
        acc.x += v0.x + v1.x;
        acc.y += v0.y + v1.y;
    }
    if (j < e) {
        int c0 = g_adj_in[j];
        float2 v0 = __ldg(&X2[(long long)c0 * 32 + lane]);
        acc.x += v0.x; acc.y += v0.y;
    }
    float inv = 1.f / (float)max(e - s, 1);
    float2 o = make_float2(acc.x * inv, acc.y * inv);
    reinterpret_cast<float2*>(g_agg)[(long long)warp * 32 + lane] = o;
}

// ---------------------------------------------------------------------------
// K6: h = relu( agg @ Wl + b + X @ Wr ).
// 64-node tile, 256 threads. Warp = 32 nodes x 16 outputs; thread = 1 node
// x 16 outputs. Weight LDS are warp-uniform (broadcast, ~free crossbar);
// a/x LDS are conflict-free LDS.32. Per k: 10 LDS (384 crossbar bytes/warp)
// -> 32 FFMA, vs old 4 LDS.128 (2KB/warp) -> 32 FFMA.
// Dynamic smem 64 KB: sWl[4096] sWr[4096] saT[4096] sxT[4096], k-major tiles.
// ---------------------------------------------------------------------------
__global__ __launch_bounds__(256) void k_h(const float* __restrict__ X,
                                           const float* __restrict__ Wl,
                                           const float* __restrict__ Wr,
                                           const float* __restrict__ b) {
    extern __shared__ float s[];
    float* sWl = s;
    float* sWr = s + 4096;
    float* saT = s + 8192;
    float* sxT = s + 12288;

    const int t = threadIdx.x;
    for (int i = t; i < 4096; i += 256) { sWl[i] = Wl[i]; sWr[i] = Wr[i]; }

    const int w    = t >> 5;            // warp 0..7
    const int lane = t & 31;
    const int nloc = (w & 1) * 32 + lane;   // node within 64-node tile
    const int jb   = (w >> 1) * 16;         // output base: 0,16,32,48

    float4 bias[4];
#pragma unroll
    for (int q = 0; q < 4; q++)
        bias[q] = reinterpret_cast<const float4*>(b)[(jb >> 2) + q];
    __syncthreads();

    const float4* A4 = reinterpret_cast<const float4*>(g_agg);
    const float4* X4 = reinterpret_cast<const float4*>(X);

    for (int base = blockIdx.x * 64; base < N_NODES; base += gridDim.x * 64) {
        // ---- load 64-node tile, transposed (k-major) ----
#pragma unroll
        for (int p = 0; p < 4; p++) {
            int fi = t + p * 256;          // 0..1023
            int node = fi & 63;
            int kq = fi >> 6;              // 0..15 (float4 index along k)
            int gnode = base + node;
            float4 va, vx;
            if (gnode < N_NODES) {
                va = A4[(long long)gnode * 16 + kq];
                vx = X4[(long long)gnode * 16 + kq];
            } else {
                va = make_float4(0.f, 0.f, 0.f, 0.f);
                vx = va;
            }
            int kb = kq * 4;
            saT[(kb + 0) * 64 + node] = va.x;
            saT[(kb + 1) * 64 + node] = va.y;
            saT[(kb + 2) * 64 + node] = va.z;
            saT[(kb + 3) * 64 + node] = va.w;
            sxT[(kb + 0) * 64 + node] = vx.x;
            sxT[(kb + 1) * 64 + node] = vx.y;
            sxT[(kb + 2) * 64 + node] = vx.z;
            sxT[(kb + 3) * 64 + node] = vx.w;
        }
        __syncthreads();

        // ---- compute 1 node x 16 outputs ----
        float acc[16];
#pragma unroll
        for (int q = 0; q < 4; q++) {
            acc[q * 4 + 0] = bias[q].x; acc[q * 4 + 1] = bias[q].y;
            acc[q * 4 + 2] = bias[q].z; acc[q * 4 + 3] = bias[q].w;
        }
#pragma unroll 4
        for (int k = 0; k < 64; k++) {
            float a = saT[k * 64 + nloc];
            float x = sxT[k * 64 + nloc];
            const float4* wl4 = reinterpret_cast<const float4*>(&sWl[k * 64 + jb]);
            const float4* wr4 = reinterpret_cast<const float4*>(&sWr[k * 64 + jb]);
#pragma unroll
            for (int q = 0; q < 4; q++) {
                float4 wl = wl4[q];
                float4 wr = wr4[q];
                acc[q * 4 + 0] += a * wl.x + x * wr.x;
                acc[q * 4 + 1] += a * wl.y + x * wr.y;
                acc[q * 4 + 2] += a * wl.z + x * wr.z;
                acc[q * 4 + 3] += a * wl.w + x * wr.w;
            }
        }

        // ---- store with ReLU ----
        int gnode = base + nloc;
        if (gnode < N_NODES) {
            float4* dst = reinterpret_cast<float4*>(&g_h[(long long)gnode * 64 + jb]);
#pragma unroll
            for (int q = 0; q < 4; q++) {
                float4 o;
                o.x = fmaxf(acc[q * 4 + 0], 0.f);
                o.y = fmaxf(acc[q * 4 + 1], 0.f);
                o.z = fmaxf(acc[q * 4 + 2], 0.f);
                o.w = fmaxf(acc[q * 4 + 3], 0.f);
                dst[q] = o;
            }
        }
        __syncthreads();
    }
}

// ---------------------------------------------------------------------------
// K7: out[r] = tanh( mean over out-neighbors of (h[r]-h[c])^2 ).
//     Warp per node; h[r] held in registers; writes final output directly.
// ---------------------------------------------------------------------------
__global__ __launch_bounds__(256) void k_edge_csr(float2* __restrict__ out) {
    int warp = (blockIdx.x * blockDim.x + threadIdx.x) >> 5;
    int lane = threadIdx.x & 31;
    if (warp >= N_NODES) return;
    const float2* h2 = reinterpret_cast<const float2*>(g_h);
    float2 hr = h2[(long long)warp * 32 + lane];
    int s = g_outptr[warp];
    int e = g_outptr[warp + 1];
    float2 acc = make_float2(0.f, 0.f);
    int j = s;
    for (; j + 1 < e; j += 2) {
        int c0 = g_adj_out[j];
        int c1 = g_adj_out[j + 1];
        float2 v0 = __ldg(&h2[(long long)c0 * 32 + lane]);
        float2 v1 = __ldg(&h2[(long long)c1 * 32 + lane]);
        float d0x = hr.x - v0.x, d0y = hr.y - v0.y;
        float d1x = hr.x - v1.x, d1y = hr.y - v1.y;
        acc.x += d0x * d0x + d1x * d1x;
        acc.y += d0y * d0y + d1y * d1y;
    }
    if (j < e) {
        int c0 = g_adj_out[j];
        float2 v0 = __ldg(&h2[(long long)c0 * 32 + lane]);
        float dx = hr.x - v0.x, dy = hr.y - v0.y;
        acc.x += dx * dx;
        acc.y += dy * dy;
    }
    float inv = 1.f / (float)max(e - s, 1);
    float2 o = make_float2(tanhf(acc.x * inv), tanhf(acc.y * inv));
    out[(long long)warp * 32 + lane] = o;
}

// ---------------------------------------------------------------------------
extern "C" void kernel_launch(void* const* d_in, const int* in_sizes, int n_in,
                              void* d_out, int out_size) {
    const float* X  = (const float*)d_in[0];
    const void*  ei = d_in[1];
    const float* Wl = (const float*)d_in[2];
    const float* Wr = (const float*)d_in[3];
    const float* b  = (const float*)d_in[4];
    float* out = (float*)d_out;

    const int KH_SMEM = 16384 * sizeof(float);   // 64 KB
    static int attr_done = 0;
    if (!attr_done) {
        cudaFuncSetAttribute(k_h, cudaFuncAttributeMaxDynamicSharedMemorySize,
                             KH_SMEM);
        attr_done = 1;
    }

    k_init<<<(N_NODES + 1023) / 1024, 1024>>>((const long long*)ei);
    k_hist<<<(N_EDGES + 511) / 512, 512>>>(ei);
    k_scan1<<<2 * NBLK, 1024>>>();
    k_scan2<<<1, 256>>>();
    k_scan3<<<2 * NBLK, 1024>>>();
    k_permute<<<(N_EDGES + 511) / 512, 512>>>(ei);
    k_agg<<<(N_NODES * 32 + 255) / 256, 256>>>((const float2*)X);
    k_h<<<444, 256, KH_SMEM>>>(X, Wl, Wr, b);
    k_edge_csr<<<(N_NODES * 32 + 255) / 256, 256>>>((float2*)out);
}